// round 4
// baseline (speedup 1.0000x reference)
#include <cuda_runtime.h>
#include <math.h>

// ---------------------------------------------------------------------------
// FormationOptimizer: fully-connected GNN, N=512, 3 message-passing rounds.
// Edge layer0 factorized: A[i] + B[j] + dist*wd. Persistent warp-specialized
// edge kernel; packed fma.rn.f32x2; duplicated H0 for MOV-free stage 2;
// all LDS tiles chosen to be crossbar-phase-minimal.
// ---------------------------------------------------------------------------

#define NN 512
#define FD 64
#define H0D 128
#define H1D 64
#define H2D 32

typedef unsigned long long ull;

__device__ float g_NF[NN * FD];
__device__ float g_DIST[NN * NN];
__device__ float g_At[H0D * NN];     // transposed: At[k][node]
__device__ float g_B[NN * H0D];      // B[node][k]
__device__ float g_AGG[NN * H2D];

__device__ __forceinline__ ull fma2(ull a, ull b, ull c) {
    ull d;
    asm("fma.rn.f32x2 %0, %1, %2, %3;" : "=l"(d) : "l"(a), "l"(b), "l"(c));
    return d;
}
__device__ __forceinline__ ull pack2(float x) {
    ull r;
    asm("mov.b64 %0, {%1, %1};" : "=l"(r) : "f"(x));
    return r;
}
__device__ __forceinline__ float2 unpack2(ull v) {
    float2 f;
    asm("mov.b64 {%0, %1}, %2;" : "=f"(f.x), "=f"(f.y) : "l"(v));
    return f;
}

// ---------------------------------------------------------------------------
__global__ void k_init(const float* __restrict__ states, const float* __restrict__ obj) {
    int i = blockIdx.x, t = threadIdx.x;
    if (t < FD) g_NF[i * FD + t] = (t < 6) ? states[i * 6 + t] : obj[t - 6];
    float px = states[i * 6 + 0], py = states[i * 6 + 1], pz = states[i * 6 + 2];
    for (int j = t; j < NN; j += blockDim.x) {
        float dx = states[j * 6 + 0] - px;
        float dy = states[j * 6 + 1] - py;
        float dz = states[j * 6 + 2] - pz;
        g_DIST[i * NN + j] = sqrtf(dx * dx + dy * dy + dz * dz);
    }
}

// ---------------------------------------------------------------------------
// k_proj: At = (nf@ew0[0:64])^T, B = nf@ew0[64:128]+eb0. Only for iter 0.
// Also zeroes g_AGG.
// ---------------------------------------------------------------------------
#define PROJ_SMEM (16384 + 512)
__global__ void __launch_bounds__(256) k_proj(const float* __restrict__ ew0,
                                              const float* __restrict__ eb0) {
    extern __shared__ float sm[];
    float* sE = sm;
    float* snf = sm + 16384;
    const int t = threadIdx.x;
    const int nb8 = blockIdx.x * 8;

    for (int q = 0; q < 16; q++)
        *(float4*)(sE + q * 1024 + t * 4) = *(const float4*)(ew0 + q * 1024 + t * 4);
    for (int q = 0; q < 2; q++) {
        int idx = q * 256 + t;
        snf[idx] = g_NF[nb8 * 64 + idx];
    }
    g_AGG[blockIdx.x * 256 + t] = 0.f;
    __syncthreads();

    const int nd = t >> 5;
    const int k4 = (t & 31) * 4;
    float4 a = make_float4(0.f, 0.f, 0.f, 0.f);
    float4 b = make_float4(0.f, 0.f, 0.f, 0.f);
#pragma unroll 4
    for (int c = 0; c < 64; c++) {
        float v = snf[nd * 64 + c];
        float4 wa = *(const float4*)(sE + c * 128 + k4);
        float4 wb = *(const float4*)(sE + (64 + c) * 128 + k4);
        a.x = fmaf(v, wa.x, a.x); a.y = fmaf(v, wa.y, a.y);
        a.z = fmaf(v, wa.z, a.z); a.w = fmaf(v, wa.w, a.w);
        b.x = fmaf(v, wb.x, b.x); b.y = fmaf(v, wb.y, b.y);
        b.z = fmaf(v, wb.z, b.z); b.w = fmaf(v, wb.w, b.w);
    }
    float4 e = *(const float4*)(eb0 + k4);
    b.x += e.x; b.y += e.y; b.z += e.z; b.w += e.w;
    int node = nb8 + nd;
    g_At[(k4 + 0) * NN + node] = a.x;
    g_At[(k4 + 1) * NN + node] = a.y;
    g_At[(k4 + 2) * NN + node] = a.z;
    g_At[(k4 + 3) * NN + node] = a.w;
    *(float4*)(g_B + node * 128 + k4) = b;
}

// ---------------------------------------------------------------------------
// k_edge: persistent, grid 148, 512 threads, 1 CTA/SM.
// Items: 2048 = 512 j x 4 sender-tiles (128 edges each).
// SMEM (floats): W1 8192 | W2 2048 | H0 dup 128x256 | H1 64x132
// ---------------------------------------------------------------------------
#define E_W1 0
#define E_W2 8192
#define E_H0 10240
#define E_H1 43008
#define E_SMEMF 51456      // 205824 bytes

#define NITEM 2048
#define EGRID 148

// stage1: compute H0 (duplicated) for one item. One warp handles KC k-rows.
template<int KC>
__device__ __forceinline__ void edge_stage1(float* __restrict__ sH0, int kbase,
                                            int j, int ibase, int lane,
                                            const float* __restrict__ wd)
{
    const float2 d0 = *(const float2*)(g_DIST + j * NN + ibase + 2 * lane);
    const float2 d1 = *(const float2*)(g_DIST + j * NN + ibase + 64 + 2 * lane);
    const float* Bj = g_B + j * H0D;
#pragma unroll
    for (int kk = 0; kk < KC; kk++) {
        const int k = kbase + kk;
        const float bk = __ldg(Bj + k);
        const float w  = __ldg(wd + k);
        float2 a0 = *(const float2*)(g_At + k * NN + ibase + 2 * lane);
        float2 a1 = *(const float2*)(g_At + k * NN + ibase + 64 + 2 * lane);
        float h00 = fmaxf(fmaf(d0.x, w, a0.x + bk), 0.f);
        float h01 = fmaxf(fmaf(d0.y, w, a0.y + bk), 0.f);
        float h10 = fmaxf(fmaf(d1.x, w, a1.x + bk), 0.f);
        float h11 = fmaxf(fmaf(d1.y, w, a1.y + bk), 0.f);
        *(float4*)(sH0 + k * 256 + 4 * lane)       = make_float4(h00, h00, h01, h01);
        *(float4*)(sH0 + k * 256 + 128 + 4 * lane) = make_float4(h10, h10, h11, h11);
    }
}

__global__ void __launch_bounds__(512, 1) k_edge(
    const float* __restrict__ ew0, const float* __restrict__ ew1,
    const float* __restrict__ eb1, const float* __restrict__ ew2,
    const float* __restrict__ eb2)
{
    extern __shared__ float sm[];
    float* sW1 = sm + E_W1;
    float* sW2 = sm + E_W2;
    float* sH0 = sm + E_H0;
    float* sH1 = sm + E_H1;

    const int t = threadIdx.x;
    const int lane = t & 31;
    const int wid = t >> 5;
    const float* wd = ew0 + 128 * H0D;

    // stage weights once
#pragma unroll
    for (int q = 0; q < 4; q++)
        *(float4*)(sW1 + q * 2048 + t * 4) = *(const float4*)(ew1 + q * 2048 + t * 4);
    *(float4*)(sW2 + t * 4) = *(const float4*)(ew2 + t * 4);

    // stage2 mapping: warp = 16e x 32n; CTA = 8 eblk x 2 nblk = 128e x 64n
    const int e0_2 = (wid >> 1) * 16 + (lane >> 3) * 4;
    const int n0   = (wid & 1) * 32 + (lane & 7) * 4;
    const ulonglong2 b1p = *(const ulonglong2*)(eb1 + n0);

    // stage3 mapping (wid<8): warp = 32e x 16m; 4 eblk x 2 mblk = 128e x 32m
    const int e0_3 = (wid >> 1) * 32 + (lane >> 2) * 4;
    const int m0   = (wid & 1) * 16 + (lane & 3) * 4;
    ulonglong2 b2p = make_ulonglong2(0ull, 0ull);
    if (wid < 8) b2p = *(const ulonglong2*)(eb2 + m0);

    int item = blockIdx.x;
    if (item < NITEM)   // prologue stage1 (all 16 warps, 8 k each)
        edge_stage1<8>(sH0, wid * 8, item >> 2, (item & 3) * 128, lane, wd);
    __syncthreads();

    while (item < NITEM) {
        const int j = item >> 2;
        const int ibase = (item & 3) * 128;

        // ---- stage 2: H1 = relu(H0 @ W1 + b1) ----
        {
            ull a00 = b1p.x, a01 = b1p.y;
            ull a10 = b1p.x, a11 = b1p.y;
            ull a20 = b1p.x, a21 = b1p.y;
            ull a30 = b1p.x, a31 = b1p.y;
#pragma unroll 4
            for (int k = 0; k < 128; k++) {
                ulonglong2 ha = *(const ulonglong2*)(sH0 + k * 256 + 2 * e0_2);
                ulonglong2 hb = *(const ulonglong2*)(sH0 + k * 256 + 2 * e0_2 + 4);
                ulonglong2 w  = *(const ulonglong2*)(sW1 + k * 64 + n0);
                a00 = fma2(ha.x, w.x, a00); a01 = fma2(ha.x, w.y, a01);
                a10 = fma2(ha.y, w.x, a10); a11 = fma2(ha.y, w.y, a11);
                a20 = fma2(hb.x, w.x, a20); a21 = fma2(hb.x, w.y, a21);
                a30 = fma2(hb.y, w.x, a30); a31 = fma2(hb.y, w.y, a31);
            }
            float r0[4], r1[4], r2[4], r3[4];
            float2 u;
            u = unpack2(a00); r0[0] = fmaxf(u.x, 0.f); r0[1] = fmaxf(u.y, 0.f);
            u = unpack2(a01); r0[2] = fmaxf(u.x, 0.f); r0[3] = fmaxf(u.y, 0.f);
            u = unpack2(a10); r1[0] = fmaxf(u.x, 0.f); r1[1] = fmaxf(u.y, 0.f);
            u = unpack2(a11); r1[2] = fmaxf(u.x, 0.f); r1[3] = fmaxf(u.y, 0.f);
            u = unpack2(a20); r2[0] = fmaxf(u.x, 0.f); r2[1] = fmaxf(u.y, 0.f);
            u = unpack2(a21); r2[2] = fmaxf(u.x, 0.f); r2[3] = fmaxf(u.y, 0.f);
            u = unpack2(a30); r3[0] = fmaxf(u.x, 0.f); r3[1] = fmaxf(u.y, 0.f);
            u = unpack2(a31); r3[2] = fmaxf(u.x, 0.f); r3[3] = fmaxf(u.y, 0.f);
#pragma unroll
            for (int q = 0; q < 4; q++)
                *(float4*)(sH1 + (n0 + q) * 132 + e0_2) =
                    make_float4(r0[q], r1[q], r2[q], r3[q]);
        }
        __syncthreads();

        const int nitem = item + EGRID;
        if (wid < 8) {
            // ---- stage 3: H2 = relu(H1 @ W2 + b2), masked aggregate ----
            ull c00 = b2p.x, c01 = b2p.y;
            ull c10 = b2p.x, c11 = b2p.y;
            ull c20 = b2p.x, c21 = b2p.y;
            ull c30 = b2p.x, c31 = b2p.y;
#pragma unroll 4
            for (int n = 0; n < 64; n++) {
                float4 h = *(const float4*)(sH1 + n * 132 + e0_3);
                ull h0 = pack2(h.x), h1 = pack2(h.y), h2 = pack2(h.z), h3 = pack2(h.w);
                ulonglong2 w = *(const ulonglong2*)(sW2 + n * 32 + m0);
                c00 = fma2(h0, w.x, c00); c01 = fma2(h0, w.y, c01);
                c10 = fma2(h1, w.x, c10); c11 = fma2(h1, w.y, c11);
                c20 = fma2(h2, w.x, c20); c21 = fma2(h2, w.y, c21);
                c30 = fma2(h3, w.x, c30); c31 = fma2(h3, w.y, c31);
            }
            const int ibe = ibase + e0_3;
            float s0 = 0.f, s1 = 0.f, s2 = 0.f, s3 = 0.f;
            float2 u0, u1;
            if (ibe + 0 != j) {
                u0 = unpack2(c00); u1 = unpack2(c01);
                s0 += fmaxf(u0.x, 0.f); s1 += fmaxf(u0.y, 0.f);
                s2 += fmaxf(u1.x, 0.f); s3 += fmaxf(u1.y, 0.f);
            }
            if (ibe + 1 != j) {
                u0 = unpack2(c10); u1 = unpack2(c11);
                s0 += fmaxf(u0.x, 0.f); s1 += fmaxf(u0.y, 0.f);
                s2 += fmaxf(u1.x, 0.f); s3 += fmaxf(u1.y, 0.f);
            }
            if (ibe + 2 != j) {
                u0 = unpack2(c20); u1 = unpack2(c21);
                s0 += fmaxf(u0.x, 0.f); s1 += fmaxf(u0.y, 0.f);
                s2 += fmaxf(u1.x, 0.f); s3 += fmaxf(u1.y, 0.f);
            }
            if (ibe + 3 != j) {
                u0 = unpack2(c30); u1 = unpack2(c31);
                s0 += fmaxf(u0.x, 0.f); s1 += fmaxf(u0.y, 0.f);
                s2 += fmaxf(u1.x, 0.f); s3 += fmaxf(u1.y, 0.f);
            }
            // reduce over the 8 edge-groups (lane bits 2..4)
#pragma unroll
            for (int off = 4; off <= 16; off <<= 1) {
                s0 += __shfl_xor_sync(0xffffffffu, s0, off);
                s1 += __shfl_xor_sync(0xffffffffu, s1, off);
                s2 += __shfl_xor_sync(0xffffffffu, s2, off);
                s3 += __shfl_xor_sync(0xffffffffu, s3, off);
            }
            if (lane < 4) {
                float* dst = g_AGG + j * H2D + m0;
                atomicAdd(dst + 0, s0);
                atomicAdd(dst + 1, s1);
                atomicAdd(dst + 2, s2);
                atomicAdd(dst + 3, s3);
            }
        } else if (nitem < NITEM) {
            // ---- stage 1 for next item (warps 8..15) ----
            edge_stage1<16>(sH0, (wid - 8) * 16, nitem >> 2, (nitem & 3) * 128,
                            lane, wd);
        }
        __syncthreads();
        item = nitem;
    }
}

// ---------------------------------------------------------------------------
// k_node: 64 CTAs x 8 nodes. Node MLP + residual, fused projection (At/B for
// next edge pass) and g_AGG zeroing.
// ---------------------------------------------------------------------------
#define NOD_W0 0
#define NOD_W1 12288
#define NOD_W2 20480
#define NOD_WO 22528
#define NOD_Y  24576
#define NOD_H0 25344
#define NOD_H1 26368
#define NOD_H2 26880
#define NOD_EW 27136
#define NOD_NF 43520
#define NODE_SMEM 44032

__global__ void __launch_bounds__(256) k_node(
    const float* __restrict__ nw0, const float* __restrict__ nb0,
    const float* __restrict__ nw1, const float* __restrict__ nb1,
    const float* __restrict__ nw2, const float* __restrict__ nb2,
    const float* __restrict__ nwo, const float* __restrict__ nbo,
    const float* __restrict__ ew0, const float* __restrict__ eb0)
{
    extern __shared__ float sm[];
    float* sw0 = sm + NOD_W0;
    float* sw1 = sm + NOD_W1;
    float* sw2 = sm + NOD_W2;
    float* swo = sm + NOD_WO;
    float* sy  = sm + NOD_Y;
    float* sh0 = sm + NOD_H0;
    float* sh1 = sm + NOD_H1;
    float* sh2 = sm + NOD_H2;
    float* sEW = sm + NOD_EW;
    float* sNF = sm + NOD_NF;

    const int t = threadIdx.x;
    const int nb8 = blockIdx.x * 8;

#pragma unroll
    for (int q = 0; q < 12; q++)
        *(float4*)(sw0 + q * 1024 + t * 4) = *(const float4*)(nw0 + q * 1024 + t * 4);
#pragma unroll
    for (int q = 0; q < 8; q++)
        *(float4*)(sw1 + q * 1024 + t * 4) = *(const float4*)(nw1 + q * 1024 + t * 4);
#pragma unroll
    for (int q = 0; q < 2; q++)
        *(float4*)(sw2 + q * 1024 + t * 4) = *(const float4*)(nw2 + q * 1024 + t * 4);
#pragma unroll
    for (int q = 0; q < 2; q++)
        *(float4*)(swo + q * 1024 + t * 4) = *(const float4*)(nwo + q * 1024 + t * 4);
#pragma unroll
    for (int q = 0; q < 16; q++)
        *(float4*)(sEW + q * 1024 + t * 4) = *(const float4*)(ew0 + q * 1024 + t * 4);
#pragma unroll
    for (int q = 0; q < 3; q++) {
        int idx = q * 256 + t;
        int nd = idx / 96, c = idx % 96;
        sy[idx] = (c < 64) ? g_NF[(nb8 + nd) * 64 + c]
                           : g_AGG[(nb8 + nd) * 32 + (c - 64)];
    }
    __syncthreads();

    const int nd = t >> 5;
    const int lane = t & 31;
    {
        const int o4 = lane * 4;
        float4 acc = *(const float4*)(nb0 + o4);
#pragma unroll 4
        for (int c = 0; c < 96; c++) {
            float v = sy[nd * 96 + c];
            float4 w = *(const float4*)(sw0 + c * 128 + o4);
            acc.x = fmaf(v, w.x, acc.x); acc.y = fmaf(v, w.y, acc.y);
            acc.z = fmaf(v, w.z, acc.z); acc.w = fmaf(v, w.w, acc.w);
        }
        acc.x = fmaxf(acc.x, 0.f); acc.y = fmaxf(acc.y, 0.f);
        acc.z = fmaxf(acc.z, 0.f); acc.w = fmaxf(acc.w, 0.f);
        *(float4*)(sh0 + nd * 128 + o4) = acc;
    }
    __syncthreads();
    {
        const int o2 = lane * 2;
        float2 acc = *(const float2*)(nb1 + o2);
#pragma unroll 4
        for (int c = 0; c < 128; c++) {
            float v = sh0[nd * 128 + c];
            float2 w = *(const float2*)(sw1 + c * 64 + o2);
            acc.x = fmaf(v, w.x, acc.x); acc.y = fmaf(v, w.y, acc.y);
        }
        acc.x = fmaxf(acc.x, 0.f); acc.y = fmaxf(acc.y, 0.f);
        *(float2*)(sh1 + nd * 64 + o2) = acc;
    }
    __syncthreads();
    {
        float acc = nb2[lane];
#pragma unroll 4
        for (int c = 0; c < 64; c++)
            acc = fmaf(sh1[nd * 64 + c], sw2[c * 32 + lane], acc);
        sh2[nd * 32 + lane] = fmaxf(acc, 0.f);
    }
    __syncthreads();
    {
        const int o2 = lane * 2;
        float2 acc = *(const float2*)(nbo + o2);
#pragma unroll 4
        for (int c = 0; c < 32; c++) {
            float v = sh2[nd * 32 + c];
            float2 w = *(const float2*)(swo + c * 64 + o2);
            acc.x = fmaf(v, w.x, acc.x); acc.y = fmaf(v, w.y, acc.y);
        }
        float2 y;
        y.x = sy[nd * 96 + o2] + acc.x;
        y.y = sy[nd * 96 + o2 + 1] + acc.y;
        *(float2*)(g_NF + (nb8 + nd) * 64 + o2) = y;
        *(float2*)(sNF + nd * 64 + o2) = y;
    }
    g_AGG[blockIdx.x * 256 + t] = 0.f;
    __syncthreads();
    // fused projection: At (transposed) and B for the next edge pass
    {
        const int k4 = lane * 4;
        float4 a = make_float4(0.f, 0.f, 0.f, 0.f);
        float4 b = make_float4(0.f, 0.f, 0.f, 0.f);
#pragma unroll 4
        for (int c = 0; c < 64; c++) {
            float v = sNF[nd * 64 + c];
            float4 wa = *(const float4*)(sEW + c * 128 + k4);
            float4 wb = *(const float4*)(sEW + (64 + c) * 128 + k4);
            a.x = fmaf(v, wa.x, a.x); a.y = fmaf(v, wa.y, a.y);
            a.z = fmaf(v, wa.z, a.z); a.w = fmaf(v, wa.w, a.w);
            b.x = fmaf(v, wb.x, b.x); b.y = fmaf(v, wb.y, b.y);
            b.z = fmaf(v, wb.z, b.z); b.w = fmaf(v, wb.w, b.w);
        }
        float4 e = *(const float4*)(eb0 + k4);
        b.x += e.x; b.y += e.y; b.z += e.z; b.w += e.w;
        int node = nb8 + nd;
        g_At[(k4 + 0) * NN + node] = a.x;
        g_At[(k4 + 1) * NN + node] = a.y;
        g_At[(k4 + 2) * NN + node] = a.z;
        g_At[(k4 + 3) * NN + node] = a.w;
        *(float4*)(g_B + node * 128 + k4) = b;
    }
}

// ---------------------------------------------------------------------------
__global__ void k_read(const float* __restrict__ rw, const float* __restrict__ rb,
                       float* __restrict__ out)
{
    int jn = blockIdx.x * blockDim.x + threadIdx.x;
    if (jn >= NN) return;
    float a0 = rb[0], a1 = rb[1], a2 = rb[2];
#pragma unroll
    for (int c = 0; c < 64; c++) {
        float v = g_NF[jn * FD + c];
        a0 = fmaf(v, rw[c * 3 + 0], a0);
        a1 = fmaf(v, rw[c * 3 + 1], a1);
        a2 = fmaf(v, rw[c * 3 + 2], a2);
    }
    out[jn * 3 + 0] = a0;
    out[jn * 3 + 1] = a1;
    out[jn * 3 + 2] = a2;
}

// ---------------------------------------------------------------------------
extern "C" void kernel_launch(void* const* d_in, const int* in_sizes, int n_in,
                              void* d_out, int out_size)
{
    const float* states = (const float*)d_in[0];
    const float* obj    = (const float*)d_in[1];
    const float* ew0 = (const float*)d_in[2];
    const float* eb0 = (const float*)d_in[3];
    const float* ew1 = (const float*)d_in[4];
    const float* eb1 = (const float*)d_in[5];
    const float* ew2 = (const float*)d_in[6];
    const float* eb2 = (const float*)d_in[7];
    const float* nw0 = (const float*)d_in[8];
    const float* nb0 = (const float*)d_in[9];
    const float* nw1 = (const float*)d_in[10];
    const float* nb1 = (const float*)d_in[11];
    const float* nw2 = (const float*)d_in[12];
    const float* nb2 = (const float*)d_in[13];
    const float* nwo = (const float*)d_in[14];
    const float* nbo = (const float*)d_in[15];
    const float* rw  = (const float*)d_in[16];
    const float* rb  = (const float*)d_in[17];
    float* out = (float*)d_out;

    cudaFuncSetAttribute(k_edge, cudaFuncAttributeMaxDynamicSharedMemorySize,
                         E_SMEMF * (int)sizeof(float));
    cudaFuncSetAttribute(k_proj, cudaFuncAttributeMaxDynamicSharedMemorySize,
                         PROJ_SMEM * (int)sizeof(float));
    cudaFuncSetAttribute(k_node, cudaFuncAttributeMaxDynamicSharedMemorySize,
                         NODE_SMEM * (int)sizeof(float));

    k_init<<<NN, 256>>>(states, obj);
    k_proj<<<64, 256, PROJ_SMEM * (int)sizeof(float)>>>(ew0, eb0);
    for (int it = 0; it < 3; it++) {
        k_edge<<<EGRID, 512, E_SMEMF * (int)sizeof(float)>>>(ew0, ew1, eb1, ew2, eb2);
        k_node<<<64, 256, NODE_SMEM * (int)sizeof(float)>>>(nw0, nb0, nw1, nb1,
                                                            nw2, nb2, nwo, nbo,
                                                            ew0, eb0);
    }
    k_read<<<4, 128>>>(rw, rb, out);
}

// round 6
// speedup vs baseline: 2.9069x; 2.9069x over previous
#include <cuda_runtime.h>
#include <math.h>
#include <stdint.h>

// ---------------------------------------------------------------------------
// FormationOptimizer: fully-connected GNN, N=512, 3 message-passing rounds.
// Edge layer0 factorized: A[i] + B[j] + dist*wd (fp32). Edge MLP GEMMs run on
// tensor cores via mma.sync.m16n8k8 tf32 (base PTX -> compiles for compute_103),
// fp32 accumulate in registers; bias/relu/mask/reduce all in-register.
// ---------------------------------------------------------------------------

#define NN 512
#define FD 64
#define H0D 128

__device__ float g_NF[NN * FD];
__device__ float g_DIST[NN * NN];
__device__ float g_A[NN * H0D];      // nf @ ew0[0:64]        [node][k]
__device__ float g_B[NN * H0D];      // nf @ ew0[64:128]+eb0  [node][k]
__device__ float g_AGG[NN * 32];

__device__ __forceinline__ uint32_t f2tf32(float x) {
    uint32_t u;
    asm("cvt.rna.tf32.f32 %0, %1;" : "=r"(u) : "f"(x));
    return u;
}
__device__ __forceinline__ void mma8(float* c, const uint32_t* a, const uint32_t* b) {
    asm volatile(
        "mma.sync.aligned.m16n8k8.row.col.f32.tf32.tf32.f32 "
        "{%0,%1,%2,%3}, {%4,%5,%6,%7}, {%8,%9}, {%0,%1,%2,%3};"
        : "+f"(c[0]), "+f"(c[1]), "+f"(c[2]), "+f"(c[3])
        : "r"(a[0]), "r"(a[1]), "r"(a[2]), "r"(a[3]), "r"(b[0]), "r"(b[1]));
}
__device__ __forceinline__ uint32_t ldsu(const float* p) {
    return __float_as_uint(*p);
}

// ---------------------------------------------------------------------------
__global__ void k_init(const float* __restrict__ states, const float* __restrict__ obj) {
    int i = blockIdx.x, t = threadIdx.x;
    if (t < FD) g_NF[i * FD + t] = (t < 6) ? states[i * 6 + t] : obj[t - 6];
    float px = states[i * 6 + 0], py = states[i * 6 + 1], pz = states[i * 6 + 2];
    for (int j = t; j < NN; j += blockDim.x) {
        float dx = states[j * 6 + 0] - px;
        float dy = states[j * 6 + 1] - py;
        float dz = states[j * 6 + 2] - pz;
        g_DIST[i * NN + j] = sqrtf(dx * dx + dy * dy + dz * dz);
    }
}

// ---------------------------------------------------------------------------
// k_proj: A/B for iteration 0, zero g_AGG.
// ---------------------------------------------------------------------------
#define PROJ_SMEM (16384 + 512)
__global__ void __launch_bounds__(256) k_proj(const float* __restrict__ ew0,
                                              const float* __restrict__ eb0) {
    extern __shared__ float sm[];
    float* sE = sm;
    float* snf = sm + 16384;
    const int t = threadIdx.x;
    const int nb8 = blockIdx.x * 8;

    for (int q = 0; q < 16; q++)
        *(float4*)(sE + q * 1024 + t * 4) = *(const float4*)(ew0 + q * 1024 + t * 4);
    for (int q = 0; q < 2; q++)
        snf[q * 256 + t] = g_NF[nb8 * 64 + q * 256 + t];
    g_AGG[blockIdx.x * 256 + t] = 0.f;
    __syncthreads();

    const int nd = t >> 5;
    const int k4 = (t & 31) * 4;
    float4 a = make_float4(0.f, 0.f, 0.f, 0.f);
    float4 b = make_float4(0.f, 0.f, 0.f, 0.f);
#pragma unroll 4
    for (int c = 0; c < 64; c++) {
        float v = snf[nd * 64 + c];
        float4 wa = *(const float4*)(sE + c * 128 + k4);
        float4 wb = *(const float4*)(sE + (64 + c) * 128 + k4);
        a.x = fmaf(v, wa.x, a.x); a.y = fmaf(v, wa.y, a.y);
        a.z = fmaf(v, wa.z, a.z); a.w = fmaf(v, wa.w, a.w);
        b.x = fmaf(v, wb.x, b.x); b.y = fmaf(v, wb.y, b.y);
        b.z = fmaf(v, wb.z, b.z); b.w = fmaf(v, wb.w, b.w);
    }
    float4 e = *(const float4*)(eb0 + k4);
    b.x += e.x; b.y += e.y; b.z += e.z; b.w += e.w;
    *(float4*)(g_A + (nb8 + nd) * 128 + k4) = a;
    *(float4*)(g_B + (nb8 + nd) * 128 + k4) = b;
}

// ---------------------------------------------------------------------------
// k_edge: persistent mma.sync tf32 kernel. grid=296 (2 CTAs/SM), 256 threads.
// Items: 4096 = 512 receivers x 8 sender-tiles (64 senders each).
// smem floats: W1t[64x132] | W2t[32x68] | H0[64x132] | H1[64x68] | wd[128]
// ---------------------------------------------------------------------------
#define S_W1T 0
#define S_W2T 8448
#define S_H0  10624
#define S_H1  19072
#define S_WD  23424
#define E_SMEMF 23552   // 94208 bytes

#define NITEM 4096
#define EGRID 296

__device__ __forceinline__ void compute_H0(float* __restrict__ sH0,
                                           const float* __restrict__ swd,
                                           int j, int ibase, int t)
{
    const int e = t & 63;
    const int kq = t >> 6;                 // 0..3 -> k block of 32
    const float d = __ldg(g_DIST + j * NN + ibase + e);
    const float4* Ap = (const float4*)(g_A + (ibase + e) * 128 + kq * 32);
    const float4* Bp = (const float4*)(g_B + j * 128 + kq * 32);
    const float4* Wp = (const float4*)(swd + kq * 32);
    float* dst = sH0 + e * 132 + kq * 32;
#pragma unroll
    for (int q = 0; q < 8; q++) {
        float4 a = __ldg(Ap + q);
        float4 b = __ldg(Bp + q);
        float4 w = Wp[q];
        float4 u;
        u.x = __uint_as_float(f2tf32(fmaxf(fmaf(d, w.x, a.x + b.x), 0.f)));
        u.y = __uint_as_float(f2tf32(fmaxf(fmaf(d, w.y, a.y + b.y), 0.f)));
        u.z = __uint_as_float(f2tf32(fmaxf(fmaf(d, w.z, a.z + b.z), 0.f)));
        u.w = __uint_as_float(f2tf32(fmaxf(fmaf(d, w.w, a.w + b.w), 0.f)));
        *(float4*)(dst + q * 4) = u;
    }
}

__global__ void __launch_bounds__(256, 2) k_edge(
    const float* __restrict__ ew0, const float* __restrict__ ew1,
    const float* __restrict__ eb1, const float* __restrict__ ew2,
    const float* __restrict__ eb2)
{
    extern __shared__ float sm[];
    float* sW1t = sm + S_W1T;
    float* sW2t = sm + S_W2T;
    float* sH0  = sm + S_H0;
    float* sH1  = sm + S_H1;
    float* swd  = sm + S_WD;

    const int t = threadIdx.x;
    const int lane = t & 31;
    const int w = t >> 5;
    const int ar = lane >> 2;          // fragment row-in-group
    const int ac = lane & 3;           // fragment col-in-group

    // ---- stage weights (transposed, tf32) once per CTA ----
    for (int idx = t; idx < 8192; idx += 256) {
        int k = idx >> 6, n = idx & 63;                 // ew1[k][n]
        sW1t[n * 132 + k] = __uint_as_float(f2tf32(__ldg(ew1 + idx)));
    }
    for (int idx = t; idx < 2048; idx += 256) {
        int k2 = idx >> 5, m = idx & 31;                // ew2[k2][m]
        sW2t[m * 68 + k2] = __uint_as_float(f2tf32(__ldg(ew2 + idx)));
    }
    if (t < 128) swd[t] = __ldg(ew0 + 128 * H0D + t);

    // GEMM1 warp tile: edges [mw, mw+32), cols [nw, nw+16)
    const int mw = (w & 1) * 32;
    const int nw = (w >> 1) * 16;
    const float e1b0 = __ldg(eb1 + nw + 2 * ac);
    const float e1b1 = __ldg(eb1 + nw + 2 * ac + 1);
    const float e1b2 = __ldg(eb1 + nw + 8 + 2 * ac);
    const float e1b3 = __ldg(eb1 + nw + 8 + 2 * ac + 1);

    // GEMM2 warp tile: edges [16*mt, +16), cols [16*nd2, +16)
    const int mt = w & 3;
    const int nd2 = w >> 2;
    const float e2b0 = __ldg(eb2 + nd2 * 16 + 2 * ac);
    const float e2b1 = __ldg(eb2 + nd2 * 16 + 2 * ac + 1);
    const float e2b2 = __ldg(eb2 + nd2 * 16 + 8 + 2 * ac);
    const float e2b3 = __ldg(eb2 + nd2 * 16 + 8 + 2 * ac + 1);

    __syncthreads();

    int item = blockIdx.x;
    if (item < NITEM)
        compute_H0(sH0, swd, item >> 3, (item & 7) * 64, t);
    __syncthreads();

    while (item < NITEM) {
        const int j = item >> 3;
        const int ibase = (item & 7) * 64;

        // ================= GEMM1: H1 = relu(H0 @ W1 + b1) =================
        {
            float acc[2][2][4];
#pragma unroll
            for (int mi = 0; mi < 2; mi++) {
                acc[mi][0][0] = e1b0; acc[mi][0][1] = e1b1;
                acc[mi][0][2] = e1b0; acc[mi][0][3] = e1b1;
                acc[mi][1][0] = e1b2; acc[mi][1][1] = e1b3;
                acc[mi][1][2] = e1b2; acc[mi][1][3] = e1b3;
            }
#pragma unroll 4
            for (int ks = 0; ks < 16; ks++) {
                const int k0 = ks * 8;
                uint32_t a[2][4], b[2][2];
#pragma unroll
                for (int mi = 0; mi < 2; mi++) {
                    const float* p = sH0 + (mw + mi * 16 + ar) * 132 + k0 + ac;
                    a[mi][0] = ldsu(p);
                    a[mi][1] = ldsu(p + 8 * 132);
                    a[mi][2] = ldsu(p + 4);
                    a[mi][3] = ldsu(p + 8 * 132 + 4);
                }
#pragma unroll
                for (int ni = 0; ni < 2; ni++) {
                    const float* p = sW1t + (nw + ni * 8 + ar) * 132 + k0 + ac;
                    b[ni][0] = ldsu(p);
                    b[ni][1] = ldsu(p + 4);
                }
#pragma unroll
                for (int mi = 0; mi < 2; mi++)
#pragma unroll
                    for (int ni = 0; ni < 2; ni++)
                        mma8(acc[mi][ni], a[mi], b[ni]);
            }
            // epilogue: relu -> tf32 -> H1
#pragma unroll
            for (int mi = 0; mi < 2; mi++) {
                const int row = mw + mi * 16 + ar;
#pragma unroll
                for (int ni = 0; ni < 2; ni++) {
                    const int col = nw + ni * 8 + 2 * ac;
                    float2 u0, u1;
                    u0.x = __uint_as_float(f2tf32(fmaxf(acc[mi][ni][0], 0.f)));
                    u0.y = __uint_as_float(f2tf32(fmaxf(acc[mi][ni][1], 0.f)));
                    u1.x = __uint_as_float(f2tf32(fmaxf(acc[mi][ni][2], 0.f)));
                    u1.y = __uint_as_float(f2tf32(fmaxf(acc[mi][ni][3], 0.f)));
                    *(float2*)(sH1 + row * 68 + col) = u0;
                    *(float2*)(sH1 + (row + 8) * 68 + col) = u1;
                }
            }
        }
        __syncthreads();

        // ================= GEMM2 + masked reduction =================
        {
            float acc[2][4];
            acc[0][0] = e2b0; acc[0][1] = e2b1; acc[0][2] = e2b0; acc[0][3] = e2b1;
            acc[1][0] = e2b2; acc[1][1] = e2b3; acc[1][2] = e2b2; acc[1][3] = e2b3;
#pragma unroll
            for (int ks = 0; ks < 8; ks++) {
                const int k0 = ks * 8;
                uint32_t a[4], b[2][2];
                const float* p = sH1 + (mt * 16 + ar) * 68 + k0 + ac;
                a[0] = ldsu(p);
                a[1] = ldsu(p + 8 * 68);
                a[2] = ldsu(p + 4);
                a[3] = ldsu(p + 8 * 68 + 4);
#pragma unroll
                for (int ni = 0; ni < 2; ni++) {
                    const float* q = sW2t + (nd2 * 16 + ni * 8 + ar) * 68 + k0 + ac;
                    b[ni][0] = ldsu(q);
                    b[ni][1] = ldsu(q + 4);
                }
                mma8(acc[0], a, b[0]);
                mma8(acc[1], a, b[1]);
            }
            const int row0 = ibase + mt * 16 + ar;
            const int row1 = row0 + 8;
            const bool k0m = (row0 != j);
            const bool k1m = (row1 != j);
#pragma unroll
            for (int ni = 0; ni < 2; ni++) {
                float v0 = k0m ? fmaxf(acc[ni][0], 0.f) : 0.f;
                float v1 = k0m ? fmaxf(acc[ni][1], 0.f) : 0.f;
                float v2 = k1m ? fmaxf(acc[ni][2], 0.f) : 0.f;
                float v3 = k1m ? fmaxf(acc[ni][3], 0.f) : 0.f;
                float s0 = v0 + v2;
                float s1 = v1 + v3;
#pragma unroll
                for (int off = 4; off <= 16; off <<= 1) {
                    s0 += __shfl_xor_sync(0xffffffffu, s0, off);
                    s1 += __shfl_xor_sync(0xffffffffu, s1, off);
                }
                if (lane < 4) {
                    const int col = nd2 * 16 + ni * 8 + 2 * ac;
                    atomicAdd(g_AGG + j * 32 + col, s0);
                    atomicAdd(g_AGG + j * 32 + col + 1, s1);
                }
            }
        }

        // next item's H0 (overlaps nothing being read: GEMM2 used H1/W2t only)
        const int nxt = item + EGRID;
        if (nxt < NITEM)
            compute_H0(sH0, swd, nxt >> 3, (nxt & 7) * 64, t);
        __syncthreads();
        item = nxt;
    }
}

// ---------------------------------------------------------------------------
// k_node: 64 CTAs x 8 nodes. Node MLP + residual, fused projection (A/B for
// next edge pass) and g_AGG zeroing.
// ---------------------------------------------------------------------------
#define NOD_W0 0
#define NOD_W1 12288
#define NOD_W2 20480
#define NOD_WO 22528
#define NOD_Y  24576
#define NOD_H0 25344
#define NOD_H1 26368
#define NOD_H2 26880
#define NOD_EW 27136
#define NOD_NF 43520
#define NODE_SMEM 44032

__global__ void __launch_bounds__(256) k_node(
    const float* __restrict__ nw0, const float* __restrict__ nb0,
    const float* __restrict__ nw1, const float* __restrict__ nb1,
    const float* __restrict__ nw2, const float* __restrict__ nb2,
    const float* __restrict__ nwo, const float* __restrict__ nbo,
    const float* __restrict__ ew0, const float* __restrict__ eb0)
{
    extern __shared__ float sm[];
    float* sw0 = sm + NOD_W0;
    float* sw1 = sm + NOD_W1;
    float* sw2 = sm + NOD_W2;
    float* swo = sm + NOD_WO;
    float* sy  = sm + NOD_Y;
    float* sh0 = sm + NOD_H0;
    float* sh1 = sm + NOD_H1;
    float* sh2 = sm + NOD_H2;
    float* sEW = sm + NOD_EW;
    float* sNF = sm + NOD_NF;

    const int t = threadIdx.x;
    const int nb8 = blockIdx.x * 8;

#pragma unroll
    for (int q = 0; q < 12; q++)
        *(float4*)(sw0 + q * 1024 + t * 4) = *(const float4*)(nw0 + q * 1024 + t * 4);
#pragma unroll
    for (int q = 0; q < 8; q++)
        *(float4*)(sw1 + q * 1024 + t * 4) = *(const float4*)(nw1 + q * 1024 + t * 4);
#pragma unroll
    for (int q = 0; q < 2; q++)
        *(float4*)(sw2 + q * 1024 + t * 4) = *(const float4*)(nw2 + q * 1024 + t * 4);
#pragma unroll
    for (int q = 0; q < 2; q++)
        *(float4*)(swo + q * 1024 + t * 4) = *(const float4*)(nwo + q * 1024 + t * 4);
#pragma unroll
    for (int q = 0; q < 16; q++)
        *(float4*)(sEW + q * 1024 + t * 4) = *(const float4*)(ew0 + q * 1024 + t * 4);
#pragma unroll
    for (int q = 0; q < 3; q++) {
        int idx = q * 256 + t;
        int nd = idx / 96, c = idx % 96;
        sy[idx] = (c < 64) ? g_NF[(nb8 + nd) * 64 + c]
                           : g_AGG[(nb8 + nd) * 32 + (c - 64)];
    }
    __syncthreads();

    const int nd = t >> 5;
    const int lane = t & 31;
    {
        const int o4 = lane * 4;
        float4 acc = *(const float4*)(nb0 + o4);
#pragma unroll 4
        for (int c = 0; c < 96; c++) {
            float v = sy[nd * 96 + c];
            float4 w = *(const float4*)(sw0 + c * 128 + o4);
            acc.x = fmaf(v, w.x, acc.x); acc.y = fmaf(v, w.y, acc.y);
            acc.z = fmaf(v, w.z, acc.z); acc.w = fmaf(v, w.w, acc.w);
        }
        acc.x = fmaxf(acc.x, 0.f); acc.y = fmaxf(acc.y, 0.f);
        acc.z = fmaxf(acc.z, 0.f); acc.w = fmaxf(acc.w, 0.f);
        *(float4*)(sh0 + nd * 128 + o4) = acc;
    }
    __syncthreads();
    {
        const int o2 = lane * 2;
        float2 acc = *(const float2*)(nb1 + o2);
#pragma unroll 4
        for (int c = 0; c < 128; c++) {
            float v = sh0[nd * 128 + c];
            float2 w = *(const float2*)(sw1 + c * 64 + o2);
            acc.x = fmaf(v, w.x, acc.x); acc.y = fmaf(v, w.y, acc.y);
        }
        acc.x = fmaxf(acc.x, 0.f); acc.y = fmaxf(acc.y, 0.f);
        *(float2*)(sh1 + nd * 64 + o2) = acc;
    }
    __syncthreads();
    {
        float acc = nb2[lane];
#pragma unroll 4
        for (int c = 0; c < 64; c++)
            acc = fmaf(sh1[nd * 64 + c], sw2[c * 32 + lane], acc);
        sh2[nd * 32 + lane] = fmaxf(acc, 0.f);
    }
    __syncthreads();
    {
        const int o2 = lane * 2;
        float2 acc = *(const float2*)(nbo + o2);
#pragma unroll 4
        for (int c = 0; c < 32; c++) {
            float v = sh2[nd * 32 + c];
            float2 w = *(const float2*)(swo + c * 64 + o2);
            acc.x = fmaf(v, w.x, acc.x); acc.y = fmaf(v, w.y, acc.y);
        }
        float2 y;
        y.x = sy[nd * 96 + o2] + acc.x;
        y.y = sy[nd * 96 + o2 + 1] + acc.y;
        *(float2*)(g_NF + (nb8 + nd) * 64 + o2) = y;
        *(float2*)(sNF + nd * 64 + o2) = y;
    }
    g_AGG[blockIdx.x * 256 + t] = 0.f;
    __syncthreads();
    // fused projection for the next edge pass
    {
        const int k4 = lane * 4;
        float4 a = make_float4(0.f, 0.f, 0.f, 0.f);
        float4 b = make_float4(0.f, 0.f, 0.f, 0.f);
#pragma unroll 4
        for (int c = 0; c < 64; c++) {
            float v = sNF[nd * 64 + c];
            float4 wa = *(const float4*)(sEW + c * 128 + k4);
            float4 wb = *(const float4*)(sEW + (64 + c) * 128 + k4);
            a.x = fmaf(v, wa.x, a.x); a.y = fmaf(v, wa.y, a.y);
            a.z = fmaf(v, wa.z, a.z); a.w = fmaf(v, wa.w, a.w);
            b.x = fmaf(v, wb.x, b.x); b.y = fmaf(v, wb.y, b.y);
            b.z = fmaf(v, wb.z, b.z); b.w = fmaf(v, wb.w, b.w);
        }
        float4 e = *(const float4*)(eb0 + k4);
        b.x += e.x; b.y += e.y; b.z += e.z; b.w += e.w;
        int node = nb8 + nd;
        *(float4*)(g_A + node * 128 + k4) = a;
        *(float4*)(g_B + node * 128 + k4) = b;
    }
}

// ---------------------------------------------------------------------------
__global__ void k_read(const float* __restrict__ rw, const float* __restrict__ rb,
                       float* __restrict__ out)
{
    int jn = blockIdx.x * blockDim.x + threadIdx.x;
    if (jn >= NN) return;
    float a0 = rb[0], a1 = rb[1], a2 = rb[2];
#pragma unroll
    for (int c = 0; c < 64; c++) {
        float v = g_NF[jn * FD + c];
        a0 = fmaf(v, rw[c * 3 + 0], a0);
        a1 = fmaf(v, rw[c * 3 + 1], a1);
        a2 = fmaf(v, rw[c * 3 + 2], a2);
    }
    out[jn * 3 + 0] = a0;
    out[jn * 3 + 1] = a1;
    out[jn * 3 + 2] = a2;
}

// ---------------------------------------------------------------------------
extern "C" void kernel_launch(void* const* d_in, const int* in_sizes, int n_in,
                              void* d_out, int out_size)
{
    const float* states = (const float*)d_in[0];
    const float* obj    = (const float*)d_in[1];
    const float* ew0 = (const float*)d_in[2];
    const float* eb0 = (const float*)d_in[3];
    const float* ew1 = (const float*)d_in[4];
    const float* eb1 = (const float*)d_in[5];
    const float* ew2 = (const float*)d_in[6];
    const float* eb2 = (const float*)d_in[7];
    const float* nw0 = (const float*)d_in[8];
    const float* nb0 = (const float*)d_in[9];
    const float* nw1 = (const float*)d_in[10];
    const float* nb1 = (const float*)d_in[11];
    const float* nw2 = (const float*)d_in[12];
    const float* nb2 = (const float*)d_in[13];
    const float* nwo = (const float*)d_in[14];
    const float* nbo = (const float*)d_in[15];
    const float* rw  = (const float*)d_in[16];
    const float* rb  = (const float*)d_in[17];
    float* out = (float*)d_out;

    cudaFuncSetAttribute(k_edge, cudaFuncAttributeMaxDynamicSharedMemorySize,
                         E_SMEMF * (int)sizeof(float));
    cudaFuncSetAttribute(k_proj, cudaFuncAttributeMaxDynamicSharedMemorySize,
                         PROJ_SMEM * (int)sizeof(float));
    cudaFuncSetAttribute(k_node, cudaFuncAttributeMaxDynamicSharedMemorySize,
                         NODE_SMEM * (int)sizeof(float));

    k_init<<<NN, 256>>>(states, obj);
    k_proj<<<64, 256, PROJ_SMEM * (int)sizeof(float)>>>(ew0, eb0);
    for (int it = 0; it < 3; it++) {
        k_edge<<<EGRID, 256, E_SMEMF * (int)sizeof(float)>>>(ew0, ew1, eb1, ew2, eb2);
        k_node<<<64, 256, NODE_SMEM * (int)sizeof(float)>>>(nw0, nb0, nw1, nb1,
                                                            nw2, nb2, nwo, nbo,
                                                            ew0, eb0);
    }
    k_read<<<4, 128>>>(rw, rb, out);
}